// round 9
// baseline (speedup 1.0000x reference)
#include <cuda_runtime.h>
#include <cuda_bf16.h>
#include <cstdint>

#define DIM   128
#define HEADS 8
#define MAXD  12
#define PADV  3
#define NTOK  256
#define MSZ   (DIM*DIM)      // 16384
#define NMAT  16             // sos (prims[-1]) unused by reference output

// ---------------- device scratch ----------------
__device__ __align__(16) float g_X [NMAT*MSZ];
__device__ __align__(16) float g_X2[NMAT*MSZ];
__device__ __align__(16) float g_T0[NMAT*MSZ];
__device__ __align__(16) float g_T1[NMAT*MSZ];
__device__ __align__(16) float g_P [NMAT*MSZ];
__device__ __align__(16) __nv_bfloat16 g_Phi [NMAT*MSZ];
__device__ __align__(16) __nv_bfloat16 g_Plo [NMAT*MSZ];
__device__ __align__(16) __nv_bfloat16 g_PThi[NMAT*MSZ];
__device__ __align__(16) __nv_bfloat16 g_PTlo[NMAT*MSZ];
__device__ int g_pw[NTOK*MAXD];
__device__ int g_depth[NTOK];

// ---------------- helpers ----------------
__device__ __forceinline__ uint32_t smem_u32(const void* p) {
    uint32_t a;
    asm("{ .reg .u64 t; cvta.to.shared.u64 t, %1; cvt.u32.u64 %0, t; }" : "=r"(a) : "l"(p));
    return a;
}
#define STS128Q(a, r0, r1, r2, r3) \
    asm volatile("st.shared.v4.b32 [%0], {%1, %2, %3, %4};" \
                 :: "r"(a), "r"(r0), "r"(r1), "r"(r2), "r"(r3) : "memory")
#define LDSM4(r0, r1, r2, r3, addr) \
    asm volatile("ldmatrix.sync.aligned.m8n8.x4.shared.b16 {%0, %1, %2, %3}, [%4];" \
                 : "=r"(r0), "=r"(r1), "=r"(r2), "=r"(r3) : "r"(addr))
#define MMA16816(d, a, b0, b1) \
    asm volatile("mma.sync.aligned.m16n8k16.row.col.f32.bf16.bf16.f32 " \
                 "{%0, %1, %2, %3}, {%4, %5, %6, %7}, {%8, %9}, {%0, %1, %2, %3};" \
                 : "+f"((d)[0]), "+f"((d)[1]), "+f"((d)[2]), "+f"((d)[3]) \
                 : "r"((a)[0]), "r"((a)[1]), "r"((a)[2]), "r"((a)[3]), \
                   "r"(b0), "r"(b1))
// pack two f32 -> bf16x2 (first arg in low half)
__device__ __forceinline__ uint32_t pack_bf2(float flo, float fhi) {
    uint32_t r;
    asm("cvt.rn.bf16x2.f32 %0, %1, %2;" : "=r"(r) : "f"(fhi), "f"(flo));
    return r;
}

// smem layout for k_maps (padded rows: 136 bf16 = 272 B; tile = 128*272 B)
#define RSB     272
#define TILE_B  34816
#define SMEM_MAPS (6*TILE_B)               // 208896 B

// load 128x128 bf16 row-major global -> padded smem rows
__device__ __forceinline__ void load_pad(uint32_t dst, const __nv_bfloat16* g,
                                         int t, int T) {
    const uint4* g4 = (const uint4*)g;
    for (int q = t; q < 2048; q += T) {
        uint4 v = g4[q];
        int r = q >> 4, c = (q & 15) << 3;
        STS128Q(dst + r * RSB + c * 2, v.x, v.y, v.z, v.w);
    }
}

// ---------------- K1: paths + steps ----------------
__global__ void k_paths(const int* __restrict__ positions,
                        float* __restrict__ steps_out, int write_steps)
{
    __shared__ int s_pw[NTOK][MAXD];
    __shared__ int s_dep[NTOK];
    int tid = threadIdx.x;
    {
        int d = positions[tid];
        int R[MAXD];
        int depth = 0;
#pragma unroll
        for (int t = 0; t < MAXD; t++) {
            if (d > 0) { R[t] = (d - 1) & 1; d = (d - 1) >> 1; depth++; }
            else       { R[t] = PADV; }
        }
#pragma unroll
        for (int t = 0; t < MAXD; t++) {
            int v = (t < depth) ? R[depth - 1 - t] : PADV;
            s_pw[tid][t] = v;
            g_pw[tid * MAXD + t] = v;
        }
        s_dep[tid] = depth;
        g_depth[tid] = depth;
    }
    __syncthreads();
    if (write_steps) {
        for (int idx = tid; idx < NTOK * NTOK; idx += blockDim.x) {
            int i = idx >> 8, j = idx & 255;
            int cpl = 0;
#pragma unroll
            for (int t = 0; t < MAXD; t++) {
                int a = s_pw[i][t];
                if (a != PADV && a == s_pw[j][t]) cpl++;
                else break;
            }
            steps_out[idx] = (float)(s_dep[i] + s_dep[j] - 2 * cpl);
        }
    }
}

// ---------------- K2a: X = (A - A^T) / 2^6 ----------------
__global__ void k_skew(const float* __restrict__ prim)
{
    int m = blockIdx.x;
    const float* A = prim + m * MSZ;
    float* X = g_X + m * MSZ;
    for (int e = threadIdx.x; e < MSZ; e += blockDim.x) {
        int i = e >> 7, j = e & 127;
        X[e] = (A[e] - A[j * DIM + i]) * (1.0f / 64.0f);
    }
}

// ---------------- K2b: expm GEMM, 32x32 C-tile, grid (16, 4, 4) -----------
// C = A@B [+ alpha*I + beta*X]; optionally T3 = c6 I + c7 X + c8 (A@B)
__global__ void __launch_bounds__(256) k_egemm3(
    const float* __restrict__ Ab, const float* __restrict__ Bb,
    float* __restrict__ Cb, const float* __restrict__ Xb,
    float alpha, float beta, float* __restrict__ T3b, int has_epi)
{
    __shared__ float As[32 * 132];
    __shared__ float Bs[128 * 36];
    const float c6 = 1.0f / 720.0f, c7 = 1.0f / 5040.0f, c8 = 1.0f / 40320.0f;
    int m  = blockIdx.x;
    int rb = blockIdx.y * 32;
    int cb = blockIdx.z * 32;
    const float* A = Ab + m * MSZ;
    const float* B = Bb + m * MSZ;
    int tid = threadIdx.x;

    for (int e = tid; e < 32 * 128; e += 256) {
        int r = e >> 7, c = e & 127;
        As[r * 132 + c] = A[(rb + r) * DIM + c];
    }
    for (int e = tid; e < 128 * 32; e += 256) {
        int r = e >> 5, c = e & 31;
        Bs[r * 36 + c] = B[r * DIM + cb + c];
    }
    __syncthreads();

    int li  = tid >> 3;             // 0..31 (row in tile)
    int lk4 = (tid & 7) * 4;        // col group of 4
    float acc[4] = {0, 0, 0, 0};

#pragma unroll 4
    for (int j = 0; j < DIM; j++) {
        float a = As[li * 132 + j];
        float4 b = *(const float4*)(Bs + j * 36 + lk4);
        acc[0] = fmaf(a, b.x, acc[0]);
        acc[1] = fmaf(a, b.y, acc[1]);
        acc[2] = fmaf(a, b.z, acc[2]);
        acc[3] = fmaf(a, b.w, acc[3]);
    }

    int gi = rb + li, gk = cb + lk4;
    float xv[4] = {0, 0, 0, 0};
    if (has_epi) {
        float4 x4 = *(const float4*)(Xb + m * MSZ + gi * DIM + gk);
        xv[0] = x4.x; xv[1] = x4.y; xv[2] = x4.z; xv[3] = x4.w;
    }
    float v[4];
#pragma unroll
    for (int c = 0; c < 4; c++) {
        float idv = (gi == gk + c) ? 1.0f : 0.0f;
        v[c] = acc[c] + (has_epi ? (alpha * idv + beta * xv[c]) : 0.0f);
    }
    *(float4*)(Cb + m * MSZ + gi * DIM + gk) = make_float4(v[0], v[1], v[2], v[3]);
    if (T3b) {
        float t[4];
#pragma unroll
        for (int c = 0; c < 4; c++) {
            float idv = (gi == gk + c) ? 1.0f : 0.0f;
            t[c] = c6 * idv + c7 * xv[c] + c8 * acc[c];
        }
        *(float4*)(T3b + m * MSZ + gi * DIM + gk) = make_float4(t[0], t[1], t[2], t[3]);
    }
}

// ---------------- K2c: split P into bf16 hi/lo (+ transposed copies) ------
__global__ void k_split()
{
    int m = blockIdx.x;
    const float* P = g_P + m * MSZ;
    for (int e = threadIdx.x; e < MSZ; e += blockDim.x) {
        int i = e >> 7, j = e & 127;
        float x = P[e];
        __nv_bfloat16 hi = __float2bfloat16(x);
        __nv_bfloat16 lo = __float2bfloat16(x - __bfloat162float(hi));
        g_Phi [m * MSZ + e] = hi;
        g_Plo [m * MSZ + e] = lo;
        g_PThi[m * MSZ + j * DIM + i] = hi;
        g_PTlo[m * MSZ + j * DIM + i] = lo;
    }
}

// ---------------- K3: maps chain, register-chained HMMA -------------------
// Warp w owns output rows w*16..w*16+15 (full 128 cols). Accumulator of step
// d is converted in-registers to the A-fragments of step d+1 (layout match:
// acc tile (m, 2k/2k+1) == A-frag (m, k)). smem holds only read-only PT(0/1)
// hi/lo + one-time P(w0) hi/lo. No syncthreads in the main loop.
__global__ void __launch_bounds__(256) k_maps_reg(float* __restrict__ out)
{
    extern __shared__ char smem[];
    uint32_t sb = smem_u32(smem);
    int tid = threadIdx.x, wid = tid >> 5, lane = tid & 31;
    int n = blockIdx.x, h = blockIdx.y;
    int depth = g_depth[n];
    float* outm = out + (size_t)(n * HEADS + h) * MSZ;

    if (depth == 0) {
        for (int e = tid; e < MSZ; e += 256)
            outm[e] = ((e >> 7) == (e & 127)) ? 1.0f : 0.0f;
        return;
    }
    const int* pw = g_pw + n * MAXD;
    if (depth == 1) {
        const float4* src = (const float4*)(g_P + (size_t)(pw[0] * HEADS + h) * MSZ);
        float4* dst = (float4*)outm;
        for (int e = tid; e < MSZ / 4; e += 256) dst[e] = src[e];
        return;
    }

    // stage: [0]=PT0hi [1]=PT0lo [2]=PT1hi [3]=PT1lo [4]=P(w0)hi [5]=P(w0)lo
    {
        size_t mb0 = (size_t)(0 * HEADS + h) * MSZ;
        size_t mb1 = (size_t)(1 * HEADS + h) * MSZ;
        size_t m0  = (size_t)(pw[0] * HEADS + h) * MSZ;
        load_pad(sb + 0 * TILE_B, g_PThi + mb0, tid, 256);
        load_pad(sb + 1 * TILE_B, g_PTlo + mb0, tid, 256);
        load_pad(sb + 2 * TILE_B, g_PThi + mb1, tid, 256);
        load_pad(sb + 3 * TILE_B, g_PTlo + mb1, tid, 256);
        load_pad(sb + 4 * TILE_B, g_Phi  + m0,  tid, 256);
        load_pad(sb + 5 * TILE_B, g_Plo  + m0,  tid, 256);
    }
    __syncthreads();

    int r0w = wid * 16;
    int t   = lane >> 3, r8 = lane & 7;
    int g   = lane >> 2, tig = lane & 3;

    // initial A-fragments from P(w0) (row-major tiles, round-8 pattern)
    uint32_t Ah[8][4], Al[8][4];
    {
        uint32_t aAddr = sb + 4 * TILE_B
                       + (uint32_t)((r0w + (t & 1) * 8 + r8) * RSB + (t >> 1) * 16);
#pragma unroll
        for (int kk = 0; kk < 8; kk++) {
            LDSM4(Ah[kk][0], Ah[kk][1], Ah[kk][2], Ah[kk][3], aAddr + kk * 32);
            LDSM4(Al[kk][0], Al[kk][1], Al[kk][2], Al[kk][3], aAddr + TILE_B + kk * 32);
        }
    }

    // B lane offset within a PT tile (round-8 pattern)
    uint32_t bOff = (uint32_t)(((t >> 1) * 8 + r8) * RSB + (t & 1) * 16);

    for (int d = 1; d < depth; d++) {
        uint32_t bHi = sb + (uint32_t)(pw[d] * 2) * TILE_B + bOff;

        float acc[16][4];
#pragma unroll
        for (int ni = 0; ni < 16; ni++)
#pragma unroll
            for (int q = 0; q < 4; q++) acc[ni][q] = 0.0f;

#pragma unroll 2
        for (int np = 0; np < 8; np++) {
            uint32_t bA = bHi + (uint32_t)(np * 16 * RSB);
#pragma unroll
            for (int kk = 0; kk < 8; kk++) {
                uint32_t b0, b1, b2, b3, c0, c1, c2, c3;
                LDSM4(b0, b1, b2, b3, bA + kk * 32);
                LDSM4(c0, c1, c2, c3, bA + TILE_B + kk * 32);
                MMA16816(acc[2*np],     Ah[kk], b0, b1);
                MMA16816(acc[2*np],     Ah[kk], c0, c1);
                MMA16816(acc[2*np],     Al[kk], b0, b1);
                MMA16816(acc[2*np + 1], Ah[kk], b2, b3);
                MMA16816(acc[2*np + 1], Ah[kk], c2, c3);
                MMA16816(acc[2*np + 1], Al[kk], b2, b3);
            }
        }

        if (d == depth - 1) {
            float* row0 = outm + (size_t)(r0w + g) * DIM;
            float* row1 = outm + (size_t)(r0w + g + 8) * DIM;
#pragma unroll
            for (int ni = 0; ni < 16; ni++) {
                int col = ni * 8 + tig * 2;
                *(float2*)(row0 + col) = make_float2(acc[ni][0], acc[ni][1]);
                *(float2*)(row1 + col) = make_float2(acc[ni][2], acc[ni][3]);
            }
        } else {
            // acc -> next-step A fragments (hi/lo split), all in registers
#pragma unroll
            for (int kk = 0; kk < 8; kk++) {
#pragma unroll
                for (int q = 0; q < 4; q++) {
                    int nt = 2 * kk + (q >> 1);
                    int bs = (q & 1) * 2;
                    float v0 = acc[nt][bs], v1 = acc[nt][bs + 1];
                    uint32_t hp = pack_bf2(v0, v1);
                    float h0 = __uint_as_float(hp << 16);
                    float h1 = __uint_as_float(hp & 0xffff0000u);
                    Ah[kk][q] = hp;
                    Al[kk][q] = pack_bf2(v0 - h0, v1 - h1);
                }
            }
        }
    }
}

// ---------------- host launcher ----------------
extern "C" void kernel_launch(void* const* d_in, const int* in_sizes, int n_in,
                              void* d_out, int out_size)
{
    const float* prim      = (const float*)d_in[0];
    const int*   positions = (const int*)d_in[1];
    float*       out       = (float*)d_out;
    (void)in_sizes; (void)n_in;

    cudaFuncSetAttribute(k_maps_reg, cudaFuncAttributeMaxDynamicSharedMemorySize, SMEM_MAPS);

    float *pX, *pX2, *pT0, *pT1, *pP;
    cudaGetSymbolAddress((void**)&pX,  g_X);
    cudaGetSymbolAddress((void**)&pX2, g_X2);
    cudaGetSymbolAddress((void**)&pT0, g_T0);
    cudaGetSymbolAddress((void**)&pT1, g_T1);
    cudaGetSymbolAddress((void**)&pP,  g_P);

    const int MAPS_ELEMS  = NTOK * HEADS * MSZ;
    const int STEPS_ELEMS = NTOK * NTOK;
    int write_steps = (out_size >= MAPS_ELEMS + STEPS_ELEMS) ? 1 : 0;
    float* steps_out = out + MAPS_ELEMS;

    k_paths<<<1, 256>>>(positions, steps_out, write_steps);

    // expm: X = skew/2^6; order-8 Taylor (Paterson-Stockmeyer); 6 squarings
    k_skew<<<NMAT, 256>>>(prim);
    const float c2 = 1.0f/2.0f, c3 = 1.0f/6.0f, c4 = 1.0f/24.0f, c5 = 1.0f/120.0f;
    dim3 gg(NMAT, 4, 4);
    k_egemm3<<<gg, 256>>>(pX,  pX,  pX2, pX, 0.0f, 0.0f, pT0, 1);
    k_egemm3<<<gg, 256>>>(pX2, pT0, pT1, pX, c4, c5, nullptr, 1);
    k_egemm3<<<gg, 256>>>(pX2, pT1, pT0, pX, c2, c3, nullptr, 1);
    k_egemm3<<<gg, 256>>>(pX2, pT0, pT1, pX, 1.0f, 1.0f, nullptr, 1);
    k_egemm3<<<gg, 256>>>(pT1, pT1, pT0, nullptr, 0, 0, nullptr, 0);
    k_egemm3<<<gg, 256>>>(pT0, pT0, pT1, nullptr, 0, 0, nullptr, 0);
    k_egemm3<<<gg, 256>>>(pT1, pT1, pT0, nullptr, 0, 0, nullptr, 0);
    k_egemm3<<<gg, 256>>>(pT0, pT0, pT1, nullptr, 0, 0, nullptr, 0);
    k_egemm3<<<gg, 256>>>(pT1, pT1, pT0, nullptr, 0, 0, nullptr, 0);
    k_egemm3<<<gg, 256>>>(pT0, pT0, pP,  nullptr, 0, 0, nullptr, 0);

    k_split<<<NMAT, 256>>>();

    dim3 gm(NTOK, HEADS);
    k_maps_reg<<<gm, 256, SMEM_MAPS>>>(out);
}

// round 10
// speedup vs baseline: 1.2818x; 1.2818x over previous
#include <cuda_runtime.h>
#include <cuda_bf16.h>
#include <cstdint>

#define DIM   128
#define HEADS 8
#define MAXD  12
#define PADV  3
#define NTOK  256
#define MSZ   (DIM*DIM)      // 16384
#define NMAT  16             // sos (prims[-1]) unused by reference output

// ---------------- device scratch ----------------
__device__ __align__(16) float g_X [NMAT*MSZ];
__device__ __align__(16) float g_X2[NMAT*MSZ];
__device__ __align__(16) float g_T0[NMAT*MSZ];
__device__ __align__(16) float g_T1[NMAT*MSZ];
__device__ __align__(16) float g_P [NMAT*MSZ];
__device__ __align__(16) __nv_bfloat16 g_Phi [NMAT*MSZ];
__device__ __align__(16) __nv_bfloat16 g_Plo [NMAT*MSZ];
__device__ __align__(16) __nv_bfloat16 g_PThi[NMAT*MSZ];
__device__ __align__(16) __nv_bfloat16 g_PTlo[NMAT*MSZ];
__device__ int g_pw[NTOK*MAXD];
__device__ int g_depth[NTOK];

// ---------------- helpers ----------------
__device__ __forceinline__ uint32_t smem_u32(const void* p) {
    uint32_t a;
    asm("{ .reg .u64 t; cvta.to.shared.u64 t, %1; cvt.u32.u64 %0, t; }" : "=r"(a) : "l"(p));
    return a;
}
#define STS128Q(a, r0, r1, r2, r3) \
    asm volatile("st.shared.v4.b32 [%0], {%1, %2, %3, %4};" \
                 :: "r"(a), "r"(r0), "r"(r1), "r"(r2), "r"(r3) : "memory")
#define LDSM4(r0, r1, r2, r3, addr) \
    asm volatile("ldmatrix.sync.aligned.m8n8.x4.shared.b16 {%0, %1, %2, %3}, [%4];" \
                 : "=r"(r0), "=r"(r1), "=r"(r2), "=r"(r3) : "r"(addr))
#define MMA16816(d, a, b0, b1) \
    asm volatile("mma.sync.aligned.m16n8k16.row.col.f32.bf16.bf16.f32 " \
                 "{%0, %1, %2, %3}, {%4, %5, %6, %7}, {%8, %9}, {%0, %1, %2, %3};" \
                 : "+f"((d)[0]), "+f"((d)[1]), "+f"((d)[2]), "+f"((d)[3]) \
                 : "r"((a)[0]), "r"((a)[1]), "r"((a)[2]), "r"((a)[3]), \
                   "r"(b0), "r"(b1))
// pack two f32 -> bf16x2 (first arg in low half)
__device__ __forceinline__ uint32_t pack_bf2(float flo, float fhi) {
    uint32_t r;
    asm("cvt.rn.bf16x2.f32 %0, %1, %2;" : "=r"(r) : "f"(fhi), "f"(flo));
    return r;
}

// smem layout for k_maps (padded rows: 136 bf16 = 272 B; tile = 128*272 B)
#define RSB     272
#define TILE_B  34816
#define SMEM_MAPS (6*TILE_B)               // 208896 B

// load 128x128 bf16 row-major global -> padded smem rows
__device__ __forceinline__ void load_pad(uint32_t dst, const __nv_bfloat16* g,
                                         int t, int T) {
    const uint4* g4 = (const uint4*)g;
    for (int q = t; q < 2048; q += T) {
        uint4 v = g4[q];
        int r = q >> 4, c = (q & 15) << 3;
        STS128Q(dst + r * RSB + c * 2, v.x, v.y, v.z, v.w);
    }
}

// ---------------- K1: paths + steps ----------------
__global__ void k_paths(const int* __restrict__ positions,
                        float* __restrict__ steps_out, int write_steps)
{
    __shared__ int s_pw[NTOK][MAXD];
    __shared__ int s_dep[NTOK];
    int tid = threadIdx.x;
    {
        int d = positions[tid];
        int R[MAXD];
        int depth = 0;
#pragma unroll
        for (int t = 0; t < MAXD; t++) {
            if (d > 0) { R[t] = (d - 1) & 1; d = (d - 1) >> 1; depth++; }
            else       { R[t] = PADV; }
        }
#pragma unroll
        for (int t = 0; t < MAXD; t++) {
            int v = (t < depth) ? R[depth - 1 - t] : PADV;
            s_pw[tid][t] = v;
            g_pw[tid * MAXD + t] = v;
        }
        s_dep[tid] = depth;
        g_depth[tid] = depth;
    }
    __syncthreads();
    if (write_steps) {
        for (int idx = tid; idx < NTOK * NTOK; idx += blockDim.x) {
            int i = idx >> 8, j = idx & 255;
            int cpl = 0;
#pragma unroll
            for (int t = 0; t < MAXD; t++) {
                int a = s_pw[i][t];
                if (a != PADV && a == s_pw[j][t]) cpl++;
                else break;
            }
            steps_out[idx] = (float)(s_dep[i] + s_dep[j] - 2 * cpl);
        }
    }
}

// ---------------- K2a: X = (A - A^T) / 2^6 ----------------
__global__ void k_skew(const float* __restrict__ prim)
{
    int m = blockIdx.x;
    const float* A = prim + m * MSZ;
    float* X = g_X + m * MSZ;
    for (int e = threadIdx.x; e < MSZ; e += blockDim.x) {
        int i = e >> 7, j = e & 127;
        X[e] = (A[e] - A[j * DIM + i]) * (1.0f / 64.0f);
    }
}

// ---------------- K2b: expm GEMM, 16x32 C-tile, grid (16, 8, 4) -----------
// C = A@B [+ alpha*I + beta*X]; optionally T3 = c6 I + c7 X + c8 (A@B)
__global__ void __launch_bounds__(256) k_egemm4(
    const float* __restrict__ Ab, const float* __restrict__ Bb,
    float* __restrict__ Cb, const float* __restrict__ Xb,
    float alpha, float beta, float* __restrict__ T3b, int has_epi)
{
    __shared__ float As[16 * 132];
    __shared__ float Bs[128 * 34];
    const float c6 = 1.0f / 720.0f, c7 = 1.0f / 5040.0f, c8 = 1.0f / 40320.0f;
    int m  = blockIdx.x;
    int rb = blockIdx.y * 16;
    int cb = blockIdx.z * 32;
    const float* A = Ab + m * MSZ;
    const float* B = Bb + m * MSZ;
    int tid = threadIdx.x;

    for (int e = tid; e < 16 * 128; e += 256) {
        int r = e >> 7, c = e & 127;
        As[r * 132 + c] = A[(rb + r) * DIM + c];
    }
    for (int e = tid; e < 128 * 32; e += 256) {
        int r = e >> 5, c = e & 31;
        Bs[r * 34 + c] = B[r * DIM + cb + c];
    }
    __syncthreads();

    int li = tid >> 4;              // 0..15 (row in tile)
    int lk = (tid & 15) * 2;        // col pair
    float acc[2] = {0, 0};

#pragma unroll 8
    for (int j = 0; j < DIM; j++) {
        float a = As[li * 132 + j];
        float2 b = *(const float2*)(Bs + j * 34 + lk);
        acc[0] = fmaf(a, b.x, acc[0]);
        acc[1] = fmaf(a, b.y, acc[1]);
    }

    int gi = rb + li, gk = cb + lk;
    float xv[2] = {0, 0};
    if (has_epi) {
        float2 x2 = *(const float2*)(Xb + m * MSZ + gi * DIM + gk);
        xv[0] = x2.x; xv[1] = x2.y;
    }
    float v[2];
#pragma unroll
    for (int c = 0; c < 2; c++) {
        float idv = (gi == gk + c) ? 1.0f : 0.0f;
        v[c] = acc[c] + (has_epi ? (alpha * idv + beta * xv[c]) : 0.0f);
    }
    *(float2*)(Cb + m * MSZ + gi * DIM + gk) = make_float2(v[0], v[1]);
    if (T3b) {
        float t[2];
#pragma unroll
        for (int c = 0; c < 2; c++) {
            float idv = (gi == gk + c) ? 1.0f : 0.0f;
            t[c] = c6 * idv + c7 * xv[c] + c8 * acc[c];
        }
        *(float2*)(T3b + m * MSZ + gi * DIM + gk) = make_float2(t[0], t[1]);
    }
}

// ---------------- K2c: split P into bf16 hi/lo (+ transposed copies) ------
__global__ void k_split()
{
    int m = blockIdx.x;
    const float* P = g_P + m * MSZ;
    for (int e = threadIdx.x; e < MSZ; e += blockDim.x) {
        int i = e >> 7, j = e & 127;
        float x = P[e];
        __nv_bfloat16 hi = __float2bfloat16(x);
        __nv_bfloat16 lo = __float2bfloat16(x - __bfloat162float(hi));
        g_Phi [m * MSZ + e] = hi;
        g_Plo [m * MSZ + e] = lo;
        g_PThi[m * MSZ + j * DIM + i] = hi;
        g_PTlo[m * MSZ + j * DIM + i] = lo;
    }
}

// ---------------- K3: maps chain, register-chained HMMA -------------------
// Warp w owns output rows w*16..w*16+15 (full 128 cols). Accumulator of step
// d is converted in-registers to the A-fragments of step d+1. smem holds only
// read-only PT(0/1) hi/lo + one-time P(w0) hi/lo. No syncthreads in the main
// loop. ALL inner loops fully unrolled so acc/Ah/Al stay in registers.
__global__ void __launch_bounds__(256) k_maps_reg(float* __restrict__ out)
{
    extern __shared__ char smem[];
    uint32_t sb = smem_u32(smem);
    int tid = threadIdx.x, wid = tid >> 5, lane = tid & 31;
    int n = blockIdx.x, h = blockIdx.y;
    int depth = g_depth[n];
    float* outm = out + (size_t)(n * HEADS + h) * MSZ;

    if (depth == 0) {
        for (int e = tid; e < MSZ; e += 256)
            outm[e] = ((e >> 7) == (e & 127)) ? 1.0f : 0.0f;
        return;
    }
    const int* pw = g_pw + n * MAXD;
    if (depth == 1) {
        const float4* src = (const float4*)(g_P + (size_t)(pw[0] * HEADS + h) * MSZ);
        float4* dst = (float4*)outm;
        for (int e = tid; e < MSZ / 4; e += 256) dst[e] = src[e];
        return;
    }

    // stage: [0]=PT0hi [1]=PT0lo [2]=PT1hi [3]=PT1lo [4]=P(w0)hi [5]=P(w0)lo
    {
        size_t mb0 = (size_t)(0 * HEADS + h) * MSZ;
        size_t mb1 = (size_t)(1 * HEADS + h) * MSZ;
        size_t m0  = (size_t)(pw[0] * HEADS + h) * MSZ;
        load_pad(sb + 0 * TILE_B, g_PThi + mb0, tid, 256);
        load_pad(sb + 1 * TILE_B, g_PTlo + mb0, tid, 256);
        load_pad(sb + 2 * TILE_B, g_PThi + mb1, tid, 256);
        load_pad(sb + 3 * TILE_B, g_PTlo + mb1, tid, 256);
        load_pad(sb + 4 * TILE_B, g_Phi  + m0,  tid, 256);
        load_pad(sb + 5 * TILE_B, g_Plo  + m0,  tid, 256);
    }
    __syncthreads();

    int r0w = wid * 16;
    int t   = lane >> 3, r8 = lane & 7;
    int g   = lane >> 2, tig = lane & 3;

    // initial A-fragments from P(w0)
    uint32_t Ah[8][4], Al[8][4];
    {
        uint32_t aAddr = sb + 4 * TILE_B
                       + (uint32_t)((r0w + (t & 1) * 8 + r8) * RSB + (t >> 1) * 16);
#pragma unroll
        for (int kk = 0; kk < 8; kk++) {
            LDSM4(Ah[kk][0], Ah[kk][1], Ah[kk][2], Ah[kk][3], aAddr + kk * 32);
            LDSM4(Al[kk][0], Al[kk][1], Al[kk][2], Al[kk][3], aAddr + TILE_B + kk * 32);
        }
    }

    // B lane offset within a PT tile
    uint32_t bOff = (uint32_t)(((t >> 1) * 8 + r8) * RSB + (t & 1) * 16);

    for (int d = 1; d < depth; d++) {
        uint32_t bHi = sb + (uint32_t)(pw[d] * 2) * TILE_B + bOff;

        float acc[16][4];
#pragma unroll
        for (int ni = 0; ni < 16; ni++)
#pragma unroll
            for (int q = 0; q < 4; q++) acc[ni][q] = 0.0f;

#pragma unroll
        for (int np = 0; np < 8; np++) {            // FULL unroll: acc indices const
            uint32_t bA = bHi + (uint32_t)(np * 16 * RSB);
#pragma unroll
            for (int kk = 0; kk < 8; kk++) {
                uint32_t b0, b1, b2, b3, c0, c1, c2, c3;
                LDSM4(b0, b1, b2, b3, bA + kk * 32);
                LDSM4(c0, c1, c2, c3, bA + TILE_B + kk * 32);
                MMA16816(acc[2*np],     Ah[kk], b0, b1);
                MMA16816(acc[2*np],     Ah[kk], c0, c1);
                MMA16816(acc[2*np],     Al[kk], b0, b1);
                MMA16816(acc[2*np + 1], Ah[kk], b2, b3);
                MMA16816(acc[2*np + 1], Ah[kk], c2, c3);
                MMA16816(acc[2*np + 1], Al[kk], b2, b3);
            }
        }

        if (d == depth - 1) {
            float* row0 = outm + (size_t)(r0w + g) * DIM;
            float* row1 = outm + (size_t)(r0w + g + 8) * DIM;
#pragma unroll
            for (int ni = 0; ni < 16; ni++) {
                int col = ni * 8 + tig * 2;
                *(float2*)(row0 + col) = make_float2(acc[ni][0], acc[ni][1]);
                *(float2*)(row1 + col) = make_float2(acc[ni][2], acc[ni][3]);
            }
        } else {
            // acc -> next-step A fragments (hi/lo split), all in registers
#pragma unroll
            for (int kk = 0; kk < 8; kk++) {
#pragma unroll
                for (int q = 0; q < 4; q++) {
                    int nt = 2 * kk + (q >> 1);
                    int bs = (q & 1) * 2;
                    float v0 = acc[nt][bs], v1 = acc[nt][bs + 1];
                    uint32_t hp = pack_bf2(v0, v1);
                    float h0 = __uint_as_float(hp << 16);
                    float h1 = __uint_as_float(hp & 0xffff0000u);
                    Ah[kk][q] = hp;
                    Al[kk][q] = pack_bf2(v0 - h0, v1 - h1);
                }
            }
        }
    }
}

// ---------------- host launcher ----------------
extern "C" void kernel_launch(void* const* d_in, const int* in_sizes, int n_in,
                              void* d_out, int out_size)
{
    const float* prim      = (const float*)d_in[0];
    const int*   positions = (const int*)d_in[1];
    float*       out       = (float*)d_out;
    (void)in_sizes; (void)n_in;

    cudaFuncSetAttribute(k_maps_reg, cudaFuncAttributeMaxDynamicSharedMemorySize, SMEM_MAPS);

    float *pX, *pX2, *pT0, *pT1, *pP;
    cudaGetSymbolAddress((void**)&pX,  g_X);
    cudaGetSymbolAddress((void**)&pX2, g_X2);
    cudaGetSymbolAddress((void**)&pT0, g_T0);
    cudaGetSymbolAddress((void**)&pT1, g_T1);
    cudaGetSymbolAddress((void**)&pP,  g_P);

    const int MAPS_ELEMS  = NTOK * HEADS * MSZ;
    const int STEPS_ELEMS = NTOK * NTOK;
    int write_steps = (out_size >= MAPS_ELEMS + STEPS_ELEMS) ? 1 : 0;
    float* steps_out = out + MAPS_ELEMS;

    k_paths<<<1, 256>>>(positions, steps_out, write_steps);

    // expm: X = skew/2^6; order-8 Taylor (Paterson-Stockmeyer); 6 squarings
    k_skew<<<NMAT, 256>>>(prim);
    const float c2 = 1.0f/2.0f, c3 = 1.0f/6.0f, c4 = 1.0f/24.0f, c5 = 1.0f/120.0f;
    dim3 gg(NMAT, 8, 4);
    k_egemm4<<<gg, 256>>>(pX,  pX,  pX2, pX, 0.0f, 0.0f, pT0, 1);
    k_egemm4<<<gg, 256>>>(pX2, pT0, pT1, pX, c4, c5, nullptr, 1);
    k_egemm4<<<gg, 256>>>(pX2, pT1, pT0, pX, c2, c3, nullptr, 1);
    k_egemm4<<<gg, 256>>>(pX2, pT0, pT1, pX, 1.0f, 1.0f, nullptr, 1);
    k_egemm4<<<gg, 256>>>(pT1, pT1, pT0, nullptr, 0, 0, nullptr, 0);
    k_egemm4<<<gg, 256>>>(pT0, pT0, pT1, nullptr, 0, 0, nullptr, 0);
    k_egemm4<<<gg, 256>>>(pT1, pT1, pT0, nullptr, 0, 0, nullptr, 0);
    k_egemm4<<<gg, 256>>>(pT0, pT0, pT1, nullptr, 0, 0, nullptr, 0);
    k_egemm4<<<gg, 256>>>(pT1, pT1, pT0, nullptr, 0, 0, nullptr, 0);
    k_egemm4<<<gg, 256>>>(pT0, pT0, pP,  nullptr, 0, 0, nullptr, 0);

    k_split<<<NMAT, 256>>>();

    dim3 gm(NTOK, HEADS);
    k_maps_reg<<<gm, 256, SMEM_MAPS>>>(out);
}

// round 11
// speedup vs baseline: 1.3558x; 1.0577x over previous
#include <cuda_runtime.h>
#include <cuda_bf16.h>
#include <cstdint>

#define DIM   128
#define HEADS 8
#define MAXD  12
#define PADV  3
#define NTOK  256
#define MSZ   (DIM*DIM)      // 16384
#define NMAT  16             // sos (prims[-1]) unused by reference output

// ---------------- device scratch ----------------
__device__ __align__(16) float g_X [NMAT*MSZ];
__device__ __align__(16) float g_X2[NMAT*MSZ];
__device__ __align__(16) float g_T0[NMAT*MSZ];
__device__ __align__(16) float g_T1[NMAT*MSZ];
__device__ __align__(16) float g_P [NMAT*MSZ];
__device__ __align__(16) __nv_bfloat16 g_Phi [NMAT*MSZ];
__device__ __align__(16) __nv_bfloat16 g_Plo [NMAT*MSZ];
__device__ __align__(16) __nv_bfloat16 g_PThi[NMAT*MSZ];
__device__ __align__(16) __nv_bfloat16 g_PTlo[NMAT*MSZ];
__device__ int g_pw[NTOK*MAXD];
__device__ int g_depth[NTOK];

// ---------------- helpers ----------------
__device__ __forceinline__ uint32_t smem_u32(const void* p) {
    uint32_t a;
    asm("{ .reg .u64 t; cvta.to.shared.u64 t, %1; cvt.u32.u64 %0, t; }" : "=r"(a) : "l"(p));
    return a;
}
#define STS128Q(a, r0, r1, r2, r3) \
    asm volatile("st.shared.v4.b32 [%0], {%1, %2, %3, %4};" \
                 :: "r"(a), "r"(r0), "r"(r1), "r"(r2), "r"(r3) : "memory")
#define LDSM4(r0, r1, r2, r3, addr) \
    asm volatile("ldmatrix.sync.aligned.m8n8.x4.shared.b16 {%0, %1, %2, %3}, [%4];" \
                 : "=r"(r0), "=r"(r1), "=r"(r2), "=r"(r3) : "r"(addr))
#define MMA16816(d, a, b0, b1) \
    asm volatile("mma.sync.aligned.m16n8k16.row.col.f32.bf16.bf16.f32 " \
                 "{%0, %1, %2, %3}, {%4, %5, %6, %7}, {%8, %9}, {%0, %1, %2, %3};" \
                 : "+f"((d)[0]), "+f"((d)[1]), "+f"((d)[2]), "+f"((d)[3]) \
                 : "r"((a)[0]), "r"((a)[1]), "r"((a)[2]), "r"((a)[3]), \
                   "r"(b0), "r"(b1))
// pack two f32 -> bf16x2 (first arg in low half)
__device__ __forceinline__ uint32_t pack_bf2(float flo, float fhi) {
    uint32_t r;
    asm("cvt.rn.bf16x2.f32 %0, %1, %2;" : "=r"(r) : "f"(fhi), "f"(flo));
    return r;
}

// smem layout for k_maps (padded rows: 136 bf16 = 272 B; tile = 128*272 B)
#define RSB     272
#define TILE_B  34816
#define SMEM_MAPS (6*TILE_B)               // 208896 B

// load 128x128 bf16 row-major global -> padded smem rows
__device__ __forceinline__ void load_pad(uint32_t dst, const __nv_bfloat16* g,
                                         int t, int T) {
    const uint4* g4 = (const uint4*)g;
    for (int q = t; q < 2048; q += T) {
        uint4 v = g4[q];
        int r = q >> 4, c = (q & 15) << 3;
        STS128Q(dst + r * RSB + c * 2, v.x, v.y, v.z, v.w);
    }
}

// ---------------- K1: paths + steps ----------------
__global__ void k_paths(const int* __restrict__ positions,
                        float* __restrict__ steps_out, int write_steps)
{
    __shared__ int s_pw[NTOK][MAXD];
    __shared__ int s_dep[NTOK];
    int tid = threadIdx.x;
    {
        int d = positions[tid];
        int R[MAXD];
        int depth = 0;
#pragma unroll
        for (int t = 0; t < MAXD; t++) {
            if (d > 0) { R[t] = (d - 1) & 1; d = (d - 1) >> 1; depth++; }
            else       { R[t] = PADV; }
        }
#pragma unroll
        for (int t = 0; t < MAXD; t++) {
            int v = (t < depth) ? R[depth - 1 - t] : PADV;
            s_pw[tid][t] = v;
            g_pw[tid * MAXD + t] = v;
        }
        s_dep[tid] = depth;
        g_depth[tid] = depth;
    }
    __syncthreads();
    if (write_steps) {
        for (int idx = tid; idx < NTOK * NTOK; idx += blockDim.x) {
            int i = idx >> 8, j = idx & 255;
            int cpl = 0;
#pragma unroll
            for (int t = 0; t < MAXD; t++) {
                int a = s_pw[i][t];
                if (a != PADV && a == s_pw[j][t]) cpl++;
                else break;
            }
            steps_out[idx] = (float)(s_dep[i] + s_dep[j] - 2 * cpl);
        }
    }
}

// ---------------- K2a: X = (A - A^T) / 2^4 ----------------
__global__ void k_skew(const float* __restrict__ prim)
{
    int m = blockIdx.x;
    const float* A = prim + m * MSZ;
    float* X = g_X + m * MSZ;
    for (int e = threadIdx.x; e < MSZ; e += blockDim.x) {
        int i = e >> 7, j = e & 127;
        X[e] = (A[e] - A[j * DIM + i]) * (1.0f / 16.0f);
    }
}

// ---------------- K2b: expm GEMM, 32x64 C-tile, grid (16, 4, 2) -----------
// C = A@B [+ alpha*I + beta*X]; optionally T3 = c6 I + c7 X + c8 (A@B)
__global__ void __launch_bounds__(256) k_egemm5(
    const float* __restrict__ Ab, const float* __restrict__ Bb,
    float* __restrict__ Cb, const float* __restrict__ Xb,
    float alpha, float beta, float* __restrict__ T3b, int has_epi)
{
    __shared__ float As[32 * 132];
    __shared__ float Bs[128 * 68];
    const float c6 = 1.0f / 720.0f, c7 = 1.0f / 5040.0f, c8 = 1.0f / 40320.0f;
    int m  = blockIdx.x;
    int rb = blockIdx.y * 32;
    int cb = blockIdx.z * 64;
    const float* A = Ab + m * MSZ;
    const float* B = Bb + m * MSZ;
    int tid = threadIdx.x;

    for (int e = tid; e < 32 * 128; e += 256) {
        int r = e >> 7, c = e & 127;
        As[r * 132 + c] = A[(rb + r) * DIM + c];
    }
    for (int e = tid; e < 128 * 64; e += 256) {
        int r = e >> 6, c = e & 63;
        Bs[r * 68 + c] = B[r * DIM + cb + c];
    }
    __syncthreads();

    int ty = tid >> 4;              // 0..15 -> 2 rows each
    int lk = (tid & 15) * 4;        // col group of 4
    int i0 = ty * 2;
    float acc[2][4];
#pragma unroll
    for (int r = 0; r < 2; r++)
#pragma unroll
        for (int c = 0; c < 4; c++) acc[r][c] = 0.0f;

#pragma unroll 4
    for (int j = 0; j < DIM; j++) {
        float a0 = As[i0 * 132 + j];
        float a1 = As[(i0 + 1) * 132 + j];
        float4 b = *(const float4*)(Bs + j * 68 + lk);
        acc[0][0] = fmaf(a0, b.x, acc[0][0]);
        acc[0][1] = fmaf(a0, b.y, acc[0][1]);
        acc[0][2] = fmaf(a0, b.z, acc[0][2]);
        acc[0][3] = fmaf(a0, b.w, acc[0][3]);
        acc[1][0] = fmaf(a1, b.x, acc[1][0]);
        acc[1][1] = fmaf(a1, b.y, acc[1][1]);
        acc[1][2] = fmaf(a1, b.z, acc[1][2]);
        acc[1][3] = fmaf(a1, b.w, acc[1][3]);
    }

#pragma unroll
    for (int r = 0; r < 2; r++) {
        int gi = rb + i0 + r, gk = cb + lk;
        float xv[4] = {0, 0, 0, 0};
        if (has_epi) {
            float4 x4 = *(const float4*)(Xb + m * MSZ + gi * DIM + gk);
            xv[0] = x4.x; xv[1] = x4.y; xv[2] = x4.z; xv[3] = x4.w;
        }
        float v[4];
#pragma unroll
        for (int c = 0; c < 4; c++) {
            float idv = (gi == gk + c) ? 1.0f : 0.0f;
            v[c] = acc[r][c] + (has_epi ? (alpha * idv + beta * xv[c]) : 0.0f);
        }
        *(float4*)(Cb + m * MSZ + gi * DIM + gk) = make_float4(v[0], v[1], v[2], v[3]);
        if (T3b) {
            float t[4];
#pragma unroll
            for (int c = 0; c < 4; c++) {
                float idv = (gi == gk + c) ? 1.0f : 0.0f;
                t[c] = c6 * idv + c7 * xv[c] + c8 * acc[r][c];
            }
            *(float4*)(T3b + m * MSZ + gi * DIM + gk) = make_float4(t[0], t[1], t[2], t[3]);
        }
    }
}

// ---------------- K2c: split P into bf16 hi/lo (+ transposed copies) ------
__global__ void k_split()
{
    int m = blockIdx.x;
    const float* P = g_P + m * MSZ;
    for (int e = threadIdx.x; e < MSZ; e += blockDim.x) {
        int i = e >> 7, j = e & 127;
        float x = P[e];
        __nv_bfloat16 hi = __float2bfloat16(x);
        __nv_bfloat16 lo = __float2bfloat16(x - __bfloat162float(hi));
        g_Phi [m * MSZ + e] = hi;
        g_Plo [m * MSZ + e] = lo;
        g_PThi[m * MSZ + j * DIM + i] = hi;
        g_PTlo[m * MSZ + j * DIM + i] = lo;
    }
}

// ---------------- K3: maps chain, register-chained HMMA -------------------
// Warp w owns output rows w*16..w*16+15. Per step, MMAs are issued as 3
// sweeps (Ah*Bh, Al*Bh, Ah*Bl) over groups of 4 np tiles so same-accumulator
// reuse distance is 8 MMAs (covers HMMA latency). No syncthreads in the loop.
__global__ void __launch_bounds__(256) k_maps_reg(float* __restrict__ out)
{
    extern __shared__ char smem[];
    uint32_t sb = smem_u32(smem);
    int tid = threadIdx.x, wid = tid >> 5, lane = tid & 31;
    int n = blockIdx.x, h = blockIdx.y;
    int depth = g_depth[n];
    float* outm = out + (size_t)(n * HEADS + h) * MSZ;

    if (depth == 0) {
        for (int e = tid; e < MSZ; e += 256)
            outm[e] = ((e >> 7) == (e & 127)) ? 1.0f : 0.0f;
        return;
    }
    const int* pw = g_pw + n * MAXD;
    if (depth == 1) {
        const float4* src = (const float4*)(g_P + (size_t)(pw[0] * HEADS + h) * MSZ);
        float4* dst = (float4*)outm;
        for (int e = tid; e < MSZ / 4; e += 256) dst[e] = src[e];
        return;
    }

    // stage: [0]=PT0hi [1]=PT0lo [2]=PT1hi [3]=PT1lo [4]=P(w0)hi [5]=P(w0)lo
    {
        size_t mb0 = (size_t)(0 * HEADS + h) * MSZ;
        size_t mb1 = (size_t)(1 * HEADS + h) * MSZ;
        size_t m0  = (size_t)(pw[0] * HEADS + h) * MSZ;
        load_pad(sb + 0 * TILE_B, g_PThi + mb0, tid, 256);
        load_pad(sb + 1 * TILE_B, g_PTlo + mb0, tid, 256);
        load_pad(sb + 2 * TILE_B, g_PThi + mb1, tid, 256);
        load_pad(sb + 3 * TILE_B, g_PTlo + mb1, tid, 256);
        load_pad(sb + 4 * TILE_B, g_Phi  + m0,  tid, 256);
        load_pad(sb + 5 * TILE_B, g_Plo  + m0,  tid, 256);
    }
    __syncthreads();

    int r0w = wid * 16;
    int t   = lane >> 3, r8 = lane & 7;
    int g   = lane >> 2, tig = lane & 3;

    // initial A-fragments from P(w0)
    uint32_t Ah[8][4], Al[8][4];
    {
        uint32_t aAddr = sb + 4 * TILE_B
                       + (uint32_t)((r0w + (t & 1) * 8 + r8) * RSB + (t >> 1) * 16);
#pragma unroll
        for (int kk = 0; kk < 8; kk++) {
            LDSM4(Ah[kk][0], Ah[kk][1], Ah[kk][2], Ah[kk][3], aAddr + kk * 32);
            LDSM4(Al[kk][0], Al[kk][1], Al[kk][2], Al[kk][3], aAddr + TILE_B + kk * 32);
        }
    }

    // B lane offset within a PT tile
    uint32_t bOff = (uint32_t)(((t >> 1) * 8 + r8) * RSB + (t & 1) * 16);

    for (int d = 1; d < depth; d++) {
        uint32_t bBase = sb + (uint32_t)(pw[d] * 2) * TILE_B + bOff;

        float acc[16][4];
#pragma unroll
        for (int ni = 0; ni < 16; ni++)
#pragma unroll
            for (int q = 0; q < 4; q++) acc[ni][q] = 0.0f;

#pragma unroll
        for (int kk = 0; kk < 8; kk++) {
#pragma unroll
            for (int gq = 0; gq < 2; gq++) {       // np groups of 4
                uint32_t Bh[4][4], Bl[4][4];
#pragma unroll
                for (int j = 0; j < 4; j++) {
                    uint32_t bA = bBase + (uint32_t)(((gq * 4 + j) * 16) * RSB) + kk * 32;
                    LDSM4(Bh[j][0], Bh[j][1], Bh[j][2], Bh[j][3], bA);
                    LDSM4(Bl[j][0], Bl[j][1], Bl[j][2], Bl[j][3], bA + TILE_B);
                }
                // sweep 1: Ah * Bh
#pragma unroll
                for (int j = 0; j < 4; j++) {
                    int np = gq * 4 + j;
                    MMA16816(acc[2*np],     Ah[kk], Bh[j][0], Bh[j][1]);
                    MMA16816(acc[2*np + 1], Ah[kk], Bh[j][2], Bh[j][3]);
                }
                // sweep 2: Al * Bh
#pragma unroll
                for (int j = 0; j < 4; j++) {
                    int np = gq * 4 + j;
                    MMA16816(acc[2*np],     Al[kk], Bh[j][0], Bh[j][1]);
                    MMA16816(acc[2*np + 1], Al[kk], Bh[j][2], Bh[j][3]);
                }
                // sweep 3: Ah * Bl
#pragma unroll
                for (int j = 0; j < 4; j++) {
                    int np = gq * 4 + j;
                    MMA16816(acc[2*np],     Ah[kk], Bl[j][0], Bl[j][1]);
                    MMA16816(acc[2*np + 1], Ah[kk], Bl[j][2], Bl[j][3]);
                }
            }
        }

        if (d == depth - 1) {
            float* row0 = outm + (size_t)(r0w + g) * DIM;
            float* row1 = outm + (size_t)(r0w + g + 8) * DIM;
#pragma unroll
            for (int ni = 0; ni < 16; ni++) {
                int col = ni * 8 + tig * 2;
                *(float2*)(row0 + col) = make_float2(acc[ni][0], acc[ni][1]);
                *(float2*)(row1 + col) = make_float2(acc[ni][2], acc[ni][3]);
            }
        } else {
            // acc -> next-step A fragments (hi/lo split), all in registers
#pragma unroll
            for (int kk = 0; kk < 8; kk++) {
#pragma unroll
                for (int q = 0; q < 4; q++) {
                    int nt = 2 * kk + (q >> 1);
                    int bs = (q & 1) * 2;
                    float v0 = acc[nt][bs], v1 = acc[nt][bs + 1];
                    uint32_t hp = pack_bf2(v0, v1);
                    float h0 = __uint_as_float(hp << 16);
                    float h1 = __uint_as_float(hp & 0xffff0000u);
                    Ah[kk][q] = hp;
                    Al[kk][q] = pack_bf2(v0 - h0, v1 - h1);
                }
            }
        }
    }
}

// ---------------- host launcher ----------------
extern "C" void kernel_launch(void* const* d_in, const int* in_sizes, int n_in,
                              void* d_out, int out_size)
{
    const float* prim      = (const float*)d_in[0];
    const int*   positions = (const int*)d_in[1];
    float*       out       = (float*)d_out;
    (void)in_sizes; (void)n_in;

    cudaFuncSetAttribute(k_maps_reg, cudaFuncAttributeMaxDynamicSharedMemorySize, SMEM_MAPS);

    float *pX, *pX2, *pT0, *pT1, *pP;
    cudaGetSymbolAddress((void**)&pX,  g_X);
    cudaGetSymbolAddress((void**)&pX2, g_X2);
    cudaGetSymbolAddress((void**)&pT0, g_T0);
    cudaGetSymbolAddress((void**)&pT1, g_T1);
    cudaGetSymbolAddress((void**)&pP,  g_P);

    const int MAPS_ELEMS  = NTOK * HEADS * MSZ;
    const int STEPS_ELEMS = NTOK * NTOK;
    int write_steps = (out_size >= MAPS_ELEMS + STEPS_ELEMS) ? 1 : 0;
    float* steps_out = out + MAPS_ELEMS;

    k_paths<<<1, 256>>>(positions, steps_out, write_steps);

    // expm: X = skew/2^4; order-8 Taylor (Paterson-Stockmeyer); 4 squarings
    k_skew<<<NMAT, 256>>>(prim);
    const float c2 = 1.0f/2.0f, c3 = 1.0f/6.0f, c4 = 1.0f/24.0f, c5 = 1.0f/120.0f;
    dim3 gg(NMAT, 4, 2);
    k_egemm5<<<gg, 256>>>(pX,  pX,  pX2, pX, 0.0f, 0.0f, pT0, 1);
    k_egemm5<<<gg, 256>>>(pX2, pT0, pT1, pX, c4, c5, nullptr, 1);
    k_egemm5<<<gg, 256>>>(pX2, pT1, pT0, pX, c2, c3, nullptr, 1);
    k_egemm5<<<gg, 256>>>(pX2, pT0, pT1, pX, 1.0f, 1.0f, nullptr, 1);
    // 4 squarings: T1 -> T0 -> T1 -> T0 -> P
    k_egemm5<<<gg, 256>>>(pT1, pT1, pT0, nullptr, 0, 0, nullptr, 0);
    k_egemm5<<<gg, 256>>>(pT0, pT0, pT1, nullptr, 0, 0, nullptr, 0);
    k_egemm5<<<gg, 256>>>(pT1, pT1, pT0, nullptr, 0, 0, nullptr, 0);
    k_egemm5<<<gg, 256>>>(pT0, pT0, pP,  nullptr, 0, 0, nullptr, 0);

    k_split<<<NMAT, 256>>>();

    dim3 gm(NTOK, HEADS);
    k_maps_reg<<<gm, 256, SMEM_MAPS>>>(out);
}

// round 12
// speedup vs baseline: 1.6091x; 1.1868x over previous
#include <cuda_runtime.h>
#include <cuda_bf16.h>
#include <cstdint>

#define DIM   128
#define HEADS 8
#define MAXD  12
#define PADV  3
#define NTOK  256
#define MSZ   (DIM*DIM)      // 16384
#define NMAT  16             // sos (prims[-1]) unused by reference output

// ---------------- device scratch ----------------
__device__ __align__(16) float g_P [NMAT*MSZ];
__device__ __align__(16) __nv_bfloat16 g_Phi[NMAT*MSZ];
__device__ __align__(16) __nv_bfloat16 g_Plo[NMAT*MSZ];
__device__ int g_pw[NTOK*MAXD];
__device__ int g_depth[NTOK];

// ---------------- helpers ----------------
__device__ __forceinline__ uint32_t smem_u32(const void* p) {
    uint32_t a;
    asm("{ .reg .u64 t; cvta.to.shared.u64 t, %1; cvt.u32.u64 %0, t; }" : "=r"(a) : "l"(p));
    return a;
}
#define STS128Q(a, r0, r1, r2, r3) \
    asm volatile("st.shared.v4.b32 [%0], {%1, %2, %3, %4};" \
                 :: "r"(a), "r"(r0), "r"(r1), "r"(r2), "r"(r3) : "memory")
#define STS32(a, v) \
    asm volatile("st.shared.b32 [%0], %1;" :: "r"(a), "r"(v) : "memory")
#define STS16(a, v) \
    asm volatile("st.shared.b16 [%0], %1;" :: "r"(a), "h"(v) : "memory")
#define LDS32(v, a) \
    asm volatile("ld.shared.b32 %0, [%1];" : "=r"(v) : "r"(a))
#define LDSM4(r0, r1, r2, r3, addr) \
    asm volatile("ldmatrix.sync.aligned.m8n8.x4.shared.b16 {%0, %1, %2, %3}, [%4];" \
                 : "=r"(r0), "=r"(r1), "=r"(r2), "=r"(r3) : "r"(addr))
#define LDSM4T(r0, r1, r2, r3, addr) \
    asm volatile("ldmatrix.sync.aligned.m8n8.x4.trans.shared.b16 {%0, %1, %2, %3}, [%4];" \
                 : "=r"(r0), "=r"(r1), "=r"(r2), "=r"(r3) : "r"(addr))
#define MMA16816(d, a, b0, b1) \
    asm volatile("mma.sync.aligned.m16n8k16.row.col.f32.bf16.bf16.f32 " \
                 "{%0, %1, %2, %3}, {%4, %5, %6, %7}, {%8, %9}, {%0, %1, %2, %3};" \
                 : "+f"((d)[0]), "+f"((d)[1]), "+f"((d)[2]), "+f"((d)[3]) \
                 : "r"((a)[0]), "r"((a)[1]), "r"((a)[2]), "r"((a)[3]), \
                   "r"(b0), "r"(b1))
// pack two f32 -> bf16x2 (first arg in low half)
__device__ __forceinline__ uint32_t pack_bf2(float flo, float fhi) {
    uint32_t r;
    asm("cvt.rn.bf16x2.f32 %0, %1, %2;" : "=r"(r) : "f"(fhi), "f"(flo));
    return r;
}

// padded rows: 136 bf16 = 272 B; tile = 128*272 B
#define RSB     272
#define TILE_B  34816
#define SMEM_EXPM (6*TILE_B)     // 208896 B
#define SMEM_MAPS (4*TILE_B)     // 139264 B

// load 128x128 bf16 row-major global -> padded smem rows
__device__ __forceinline__ void load_pad(uint32_t dst, const __nv_bfloat16* g,
                                         int t, int T) {
    const uint4* g4 = (const uint4*)g;
    for (int q = t; q < 2048; q += T) {
        uint4 v = g4[q];
        int r = q >> 4, c = (q & 15) << 3;
        STS128Q(dst + r * RSB + c * 2, v.x, v.y, v.z, v.w);
    }
}

// ---- 3-pass bf16 HMMA: acc(16x[4]) = Arows(16) @ B(128x128), B row-major in
// smem (rows = k index), fragments fetched via ldmatrix.trans. bSlot = hi base;
// lo at +TILE_B. bT = lane offset: ((t&1)*8+r8)*RSB + (t>>1)*16.
__device__ __forceinline__ void gemm3(float acc[16][4],
                                      const uint32_t Ah[8][4],
                                      const uint32_t Al[8][4],
                                      uint32_t bSlot, uint32_t bT)
{
#pragma unroll
    for (int ni = 0; ni < 16; ni++)
#pragma unroll
        for (int q = 0; q < 4; q++) acc[ni][q] = 0.0f;

#pragma unroll
    for (int kk = 0; kk < 8; kk++) {
#pragma unroll
        for (int gq = 0; gq < 2; gq++) {
            uint32_t Bh[4][4], Bl[4][4];
#pragma unroll
            for (int j = 0; j < 4; j++) {
                uint32_t bA = bSlot + bT + (uint32_t)(kk * 16 * RSB)
                            + (uint32_t)((gq * 4 + j) * 32);
                LDSM4T(Bh[j][0], Bh[j][1], Bh[j][2], Bh[j][3], bA);
                LDSM4T(Bl[j][0], Bl[j][1], Bl[j][2], Bl[j][3], bA + TILE_B);
            }
#pragma unroll
            for (int j = 0; j < 4; j++) {
                int np = gq * 4 + j;
                MMA16816(acc[2*np],     Ah[kk], Bh[j][0], Bh[j][1]);
                MMA16816(acc[2*np + 1], Ah[kk], Bh[j][2], Bh[j][3]);
            }
#pragma unroll
            for (int j = 0; j < 4; j++) {
                int np = gq * 4 + j;
                MMA16816(acc[2*np],     Al[kk], Bh[j][0], Bh[j][1]);
                MMA16816(acc[2*np + 1], Al[kk], Bh[j][2], Bh[j][3]);
            }
#pragma unroll
            for (int j = 0; j < 4; j++) {
                int np = gq * 4 + j;
                MMA16816(acc[2*np],     Ah[kk], Bl[j][0], Bl[j][1]);
                MMA16816(acc[2*np + 1], Ah[kk], Bl[j][2], Bl[j][3]);
            }
        }
    }
}

// acc -> next-step A fragments (hi/lo split), all in registers
__device__ __forceinline__ void conv_frags(const float acc[16][4],
                                           uint32_t Ah[8][4], uint32_t Al[8][4])
{
#pragma unroll
    for (int kk = 0; kk < 8; kk++) {
#pragma unroll
        for (int q = 0; q < 4; q++) {
            int nt = 2 * kk + (q >> 1);
            int bs = (q & 1) * 2;
            float v0 = acc[nt][bs], v1 = acc[nt][bs + 1];
            uint32_t hp = pack_bf2(v0, v1);
            float h0 = __uint_as_float(hp << 16);
            float h1 = __uint_as_float(hp & 0xffff0000u);
            Ah[kk][q] = hp;
            Al[kk][q] = pack_bf2(v0 - h0, v1 - h1);
        }
    }
}

// acc := cA*acc + cX*X + cI*I  (X read as hi+lo pairs from smem slots)
__device__ __forceinline__ void epi_inplace(float acc[16][4],
    float cA, float cX, float cI, uint32_t xSlot, int r0w, int g, int tig)
{
    int r0 = r0w + g, r1 = r0w + g + 8;
#pragma unroll
    for (int ni = 0; ni < 16; ni++) {
        int col = ni * 8 + tig * 2;
        uint32_t a0 = xSlot + (uint32_t)(r0 * RSB + col * 2);
        uint32_t a1 = xSlot + (uint32_t)(r1 * RSB + col * 2);
        uint32_t h0, l0, h1, l1;
        LDS32(h0, a0); LDS32(l0, a0 + TILE_B);
        LDS32(h1, a1); LDS32(l1, a1 + TILE_B);
        float x00 = __uint_as_float(h0 << 16) + __uint_as_float(l0 << 16);
        float x01 = __uint_as_float(h0 & 0xffff0000u) + __uint_as_float(l0 & 0xffff0000u);
        float x10 = __uint_as_float(h1 << 16) + __uint_as_float(l1 << 16);
        float x11 = __uint_as_float(h1 & 0xffff0000u) + __uint_as_float(l1 & 0xffff0000u);
        acc[ni][0] = cA * acc[ni][0] + cX * x00 + ((r0 == col)     ? cI : 0.0f);
        acc[ni][1] = cA * acc[ni][1] + cX * x01 + ((r0 == col + 1) ? cI : 0.0f);
        acc[ni][2] = cA * acc[ni][2] + cX * x10 + ((r1 == col)     ? cI : 0.0f);
        acc[ni][3] = cA * acc[ni][3] + cX * x11 + ((r1 == col + 1) ? cI : 0.0f);
    }
}

// store acc (fp32) as bf16 hi/lo row-major into smem slot
__device__ __forceinline__ void store_buf(const float acc[16][4],
    uint32_t slot, int r0w, int g, int tig)
{
    int r0 = r0w + g, r1 = r0w + g + 8;
#pragma unroll
    for (int ni = 0; ni < 16; ni++) {
        int col = ni * 8 + tig * 2;
        float v0 = acc[ni][0], v1 = acc[ni][1];
        float v2 = acc[ni][2], v3 = acc[ni][3];
        uint32_t hp01 = pack_bf2(v0, v1), hp23 = pack_bf2(v2, v3);
        uint32_t lp01 = pack_bf2(v0 - __uint_as_float(hp01 << 16),
                                 v1 - __uint_as_float(hp01 & 0xffff0000u));
        uint32_t lp23 = pack_bf2(v2 - __uint_as_float(hp23 << 16),
                                 v3 - __uint_as_float(hp23 & 0xffff0000u));
        uint32_t a0 = slot + (uint32_t)(r0 * RSB + col * 2);
        uint32_t a1 = slot + (uint32_t)(r1 * RSB + col * 2);
        STS32(a0, hp01); STS32(a0 + TILE_B, lp01);
        STS32(a1, hp23); STS32(a1 + TILE_B, lp23);
    }
}

// ---------------- K1: paths + steps ----------------
__global__ void k_paths(const int* __restrict__ positions,
                        float* __restrict__ steps_out, int write_steps)
{
    __shared__ int s_pw[NTOK][MAXD];
    __shared__ int s_dep[NTOK];
    int tid = threadIdx.x;
    {
        int d = positions[tid];
        int R[MAXD];
        int depth = 0;
#pragma unroll
        for (int t = 0; t < MAXD; t++) {
            if (d > 0) { R[t] = (d - 1) & 1; d = (d - 1) >> 1; depth++; }
            else       { R[t] = PADV; }
        }
#pragma unroll
        for (int t = 0; t < MAXD; t++) {
            int v = (t < depth) ? R[depth - 1 - t] : PADV;
            s_pw[tid][t] = v;
            g_pw[tid * MAXD + t] = v;
        }
        s_dep[tid] = depth;
        g_depth[tid] = depth;
    }
    __syncthreads();
    if (write_steps) {
        for (int idx = tid; idx < NTOK * NTOK; idx += blockDim.x) {
            int i = idx >> 8, j = idx & 255;
            int cpl = 0;
#pragma unroll
            for (int t = 0; t < MAXD; t++) {
                int a = s_pw[i][t];
                if (a != PADV && a == s_pw[j][t]) cpl++;
                else break;
            }
            steps_out[idx] = (float)(s_dep[i] + s_dep[j] - 2 * cpl);
        }
    }
}

// ---------------- K2: fused expm (one CTA per matrix) ----------------
// X = skew(A)/16 -> Paterson-Stockmeyer order 8 -> 4 squarings.
// All GEMMs 3-pass bf16 HMMA; intermediates live in smem as bf16 hi/lo.
// Writes g_P (f32) and g_Phi/g_Plo (bf16 split).
// smem slots: [0]=Xh [1]=Xl [2]=B0h [3]=B0l [4]=B1h [5]=B1l
__global__ void __launch_bounds__(256) k_expm(const float* __restrict__ prim)
{
    extern __shared__ char smem[];
    uint32_t sb = smem_u32(smem);
    int tid = threadIdx.x, wid = tid >> 5, lane = tid & 31;
    int m = blockIdx.x;
    const float* A = prim + (size_t)m * MSZ;

    // skew + split -> Xh/Xl (row-major)
    for (int e = tid; e < MSZ; e += 256) {
        int i = e >> 7, j = e & 127;
        float x = (A[e] - A[j * DIM + i]) * (1.0f / 16.0f);
        __nv_bfloat16 hb = __float2bfloat16(x);
        float hf = __bfloat162float(hb);
        __nv_bfloat16 lb = __float2bfloat16(x - hf);
        uint32_t ad = sb + (uint32_t)(i * RSB + j * 2);
        STS16(ad, (unsigned short)__bfloat16_as_ushort(hb));
        STS16(ad + TILE_B, (unsigned short)__bfloat16_as_ushort(lb));
    }
    __syncthreads();

    int r0w = wid * 16;
    int t   = lane >> 3, r8 = lane & 7;
    int g   = lane >> 2, tig = lane & 3;
    uint32_t aOff = (uint32_t)((r0w + (t & 1) * 8 + r8) * RSB + (t >> 1) * 16);
    uint32_t bT   = (uint32_t)(((t & 1) * 8 + r8) * RSB + (t >> 1) * 16);
    uint32_t slotX  = sb + 0 * TILE_B;
    uint32_t slotB0 = sb + 2 * TILE_B;
    uint32_t slotB1 = sb + 4 * TILE_B;

    const float c2 = 1.0f/2.0f, c3 = 1.0f/6.0f, c4 = 1.0f/24.0f, c5 = 1.0f/120.0f;
    const float c6 = 1.0f/720.0f, c7 = 1.0f/5040.0f, c8 = 1.0f/40320.0f;

    // A-frags of X
    uint32_t Xa[8][4], Xal[8][4];
#pragma unroll
    for (int kk = 0; kk < 8; kk++) {
        LDSM4(Xa[kk][0], Xa[kk][1], Xa[kk][2], Xa[kk][3], slotX + aOff + kk * 32);
        LDSM4(Xal[kk][0], Xal[kk][1], Xal[kk][2], Xal[kk][3],
              slotX + TILE_B + aOff + kk * 32);
    }

    float acc[16][4];
    uint32_t X2h[8][4], X2l[8][4];

    // X2 = X @ X
    gemm3(acc, Xa, Xal, slotX, bT);
    conv_frags(acc, X2h, X2l);
    // T3 = c6 I + c7 X + c8 X2 -> B0
    epi_inplace(acc, c8, c7, c6, slotX, r0w, g, tig);
    store_buf(acc, slotB0, r0w, g, tig);
    __syncthreads();
    // T2 = X2@T3 + c4 I + c5 X -> B1
    gemm3(acc, X2h, X2l, slotB0, bT);
    epi_inplace(acc, 1.0f, c5, c4, slotX, r0w, g, tig);
    store_buf(acc, slotB1, r0w, g, tig);
    __syncthreads();
    // T1 = X2@T2 + c2 I + c3 X -> B0
    gemm3(acc, X2h, X2l, slotB1, bT);
    epi_inplace(acc, 1.0f, c3, c2, slotX, r0w, g, tig);
    store_buf(acc, slotB0, r0w, g, tig);
    __syncthreads();
    // S = X2@T1 + I + X -> B1 (+frags)
    gemm3(acc, X2h, X2l, slotB0, bT);
    epi_inplace(acc, 1.0f, 1.0f, 1.0f, slotX, r0w, g, tig);
    store_buf(acc, slotB1, r0w, g, tig);
    uint32_t Sh[8][4], Sl[8][4];
    conv_frags(acc, Sh, Sl);
    __syncthreads();

    // 4 squarings, register-chained
#pragma unroll
    for (int q = 0; q < 4; q++) {
        uint32_t rd = (q & 1) ? slotB0 : slotB1;
        uint32_t wr = (q & 1) ? slotB1 : slotB0;
        gemm3(acc, Sh, Sl, rd, bT);
        conv_frags(acc, Sh, Sl);
        if (q < 3) {
            store_buf(acc, wr, r0w, g, tig);
            __syncthreads();
        }
    }

    // final write: g_P (f32), g_Phi/g_Plo (bf16 split)
    {
        float* Pm = g_P + (size_t)m * MSZ;
        __nv_bfloat16* Ph = g_Phi + (size_t)m * MSZ;
        __nv_bfloat16* Pl = g_Plo + (size_t)m * MSZ;
        int r0 = r0w + g, r1 = r0w + g + 8;
#pragma unroll
        for (int ni = 0; ni < 16; ni++) {
            int col = ni * 8 + tig * 2;
            float v0 = acc[ni][0], v1 = acc[ni][1];
            float v2 = acc[ni][2], v3 = acc[ni][3];
            *(float2*)(Pm + (size_t)r0 * DIM + col) = make_float2(v0, v1);
            *(float2*)(Pm + (size_t)r1 * DIM + col) = make_float2(v2, v3);
            uint32_t hp01 = pack_bf2(v0, v1), hp23 = pack_bf2(v2, v3);
            uint32_t lp01 = pack_bf2(v0 - __uint_as_float(hp01 << 16),
                                     v1 - __uint_as_float(hp01 & 0xffff0000u));
            uint32_t lp23 = pack_bf2(v2 - __uint_as_float(hp23 << 16),
                                     v3 - __uint_as_float(hp23 & 0xffff0000u));
            *(uint32_t*)(Ph + (size_t)r0 * DIM + col) = hp01;
            *(uint32_t*)(Ph + (size_t)r1 * DIM + col) = hp23;
            *(uint32_t*)(Pl + (size_t)r0 * DIM + col) = lp01;
            *(uint32_t*)(Pl + (size_t)r1 * DIM + col) = lp23;
        }
    }
}

// ---------------- K3: maps chain, register-chained HMMA -------------------
// B operands via ldmatrix.trans from row-major Phi/Plo tiles.
// smem slots: [0]=P0h [1]=P0l [2]=P1h [3]=P1l
__global__ void __launch_bounds__(256) k_maps_reg(float* __restrict__ out)
{
    extern __shared__ char smem[];
    uint32_t sb = smem_u32(smem);
    int tid = threadIdx.x, wid = tid >> 5, lane = tid & 31;
    int n = blockIdx.x, h = blockIdx.y;
    int depth = g_depth[n];
    float* outm = out + (size_t)(n * HEADS + h) * MSZ;

    if (depth == 0) {
        for (int e = tid; e < MSZ; e += 256)
            outm[e] = ((e >> 7) == (e & 127)) ? 1.0f : 0.0f;
        return;
    }
    const int* pw = g_pw + n * MAXD;
    if (depth == 1) {
        const float4* src = (const float4*)(g_P + (size_t)(pw[0] * HEADS + h) * MSZ);
        float4* dst = (float4*)outm;
        for (int e = tid; e < MSZ / 4; e += 256) dst[e] = src[e];
        return;
    }

    {
        size_t mb0 = (size_t)(0 * HEADS + h) * MSZ;
        size_t mb1 = (size_t)(1 * HEADS + h) * MSZ;
        load_pad(sb + 0 * TILE_B, g_Phi + mb0, tid, 256);
        load_pad(sb + 1 * TILE_B, g_Plo + mb0, tid, 256);
        load_pad(sb + 2 * TILE_B, g_Phi + mb1, tid, 256);
        load_pad(sb + 3 * TILE_B, g_Plo + mb1, tid, 256);
    }
    __syncthreads();

    int r0w = wid * 16;
    int t   = lane >> 3, r8 = lane & 7;
    int g   = lane >> 2, tig = lane & 3;
    uint32_t aOff = (uint32_t)((r0w + (t & 1) * 8 + r8) * RSB + (t >> 1) * 16);
    uint32_t bT   = (uint32_t)(((t & 1) * 8 + r8) * RSB + (t >> 1) * 16);

    // initial A-frags from P(w0) -- already staged (w0 is 0 or 1)
    uint32_t Ah[8][4], Al[8][4];
    {
        uint32_t slot = sb + (uint32_t)(pw[0] * 2) * TILE_B;
#pragma unroll
        for (int kk = 0; kk < 8; kk++) {
            LDSM4(Ah[kk][0], Ah[kk][1], Ah[kk][2], Ah[kk][3], slot + aOff + kk * 32);
            LDSM4(Al[kk][0], Al[kk][1], Al[kk][2], Al[kk][3],
                  slot + TILE_B + aOff + kk * 32);
        }
    }

    float acc[16][4];
    for (int d = 1; d < depth; d++) {
        uint32_t slot = sb + (uint32_t)(pw[d] * 2) * TILE_B;
        gemm3(acc, Ah, Al, slot, bT);
        if (d == depth - 1) {
            float* row0 = outm + (size_t)(r0w + g) * DIM;
            float* row1 = outm + (size_t)(r0w + g + 8) * DIM;
#pragma unroll
            for (int ni = 0; ni < 16; ni++) {
                int col = ni * 8 + tig * 2;
                *(float2*)(row0 + col) = make_float2(acc[ni][0], acc[ni][1]);
                *(float2*)(row1 + col) = make_float2(acc[ni][2], acc[ni][3]);
            }
        } else {
            conv_frags(acc, Ah, Al);
        }
    }
}

// ---------------- host launcher ----------------
extern "C" void kernel_launch(void* const* d_in, const int* in_sizes, int n_in,
                              void* d_out, int out_size)
{
    const float* prim      = (const float*)d_in[0];
    const int*   positions = (const int*)d_in[1];
    float*       out       = (float*)d_out;
    (void)in_sizes; (void)n_in;

    cudaFuncSetAttribute(k_expm, cudaFuncAttributeMaxDynamicSharedMemorySize, SMEM_EXPM);
    cudaFuncSetAttribute(k_maps_reg, cudaFuncAttributeMaxDynamicSharedMemorySize, SMEM_MAPS);

    const int MAPS_ELEMS  = NTOK * HEADS * MSZ;
    const int STEPS_ELEMS = NTOK * NTOK;
    int write_steps = (out_size >= MAPS_ELEMS + STEPS_ELEMS) ? 1 : 0;
    float* steps_out = out + MAPS_ELEMS;

    k_paths<<<1, 256>>>(positions, steps_out, write_steps);
    k_expm<<<NMAT, 256, SMEM_EXPM>>>(prim);
    dim3 gm(NTOK, HEADS);
    k_maps_reg<<<gm, 256, SMEM_MAPS>>>(out);
}